// round 8
// baseline (speedup 1.0000x reference)
#include <cuda_runtime.h>
#include <cstdint>
#include <math.h>

#define BN_EPS 1e-5f
#define FULL 0xFFFFFFFFu

__global__ __launch_bounds__(512) void bnn_kernel(
    const float* __restrict__ x,
    const float* __restrict__ conv_w, const float* __restrict__ conv_b,
    const float* __restrict__ g2, const float* __restrict__ b2,
    const float* __restrict__ m2, const float* __restrict__ v2,
    const float* __restrict__ fc_w, const float* __restrict__ fc_b,
    const float* __restrict__ g1, const float* __restrict__ b1,
    const float* __restrict__ m1, const float* __restrict__ v1,
    float* __restrict__ out, int B)
{
    __shared__ uint32_t s_cwlo[5], s_cwhi[5];   // conv sign bits
    __shared__ float4   s_bn2[5];               // (conv_b, m2, g2/sqrt(v2+eps), b2) [fallback]
    __shared__ int      s_thrA[5], s_thrB[5];   // min even S with y>0 / max even S with y<0
    __shared__ uint32_t s_fcw[10][5];           // fc sign bits
    __shared__ float2   s_fcz[10];              // z = dot*scale + shift

    const int tid  = threadIdx.x;
    const int lane = tid & 31;
    int img = blockIdx.x * 16 + (tid >> 5);
    const bool valid = (img < B);
    if (!valid) img = B - 1;                    // clamp: safe loads, store guarded

    const float* __restrict__ xb = x + (size_t)img * 784;

    // ================= prep phase 0: zero atomic targets =================
    if (tid < 5) { s_cwlo[tid] = 0; s_cwhi[tid] = 0; s_thrA[tid] = 1000; s_thrB[tid] = -1000; }
    if (tid >= 32 && tid < 82) ((uint32_t*)s_fcw)[tid - 32] = 0;
    __syncthreads();

    // ================= prep phase 1: fully parallel (smem atomics) =================
    if (tid < 180) {                            // conv weight bits: one element each
        const int c = tid / 36, k = tid % 36, ky = k / 6, kx = k % 6;
        if (conv_w[tid] > 0.f) {
            if (ky < 5) atomicOr(&s_cwlo[c], 1u << k);
            else        atomicOr(&s_cwhi[c], 1u << kx);
        }
    }
    if (tid < 250) {                            // fc weight bits: 5 elements, same word
        const int e0 = tid * 5;
        const int j = e0 / 125, rem = e0 % 125, c = rem / 25, q0 = rem % 25;
        uint32_t wv = 0;
        #pragma unroll
        for (int i = 0; i < 5; i++)
            if (fc_w[e0 + i] > 0.f) wv |= 1u << (q0 + i);
        if (wv) atomicOr(&s_fcw[j][c], wv);
    }
    if (tid >= 256 && tid < 441) {              // threshold scan: one (c, S) each
        const int i = tid - 256, c = i / 37, S = -36 + 2 * (i % 37);
        float scl = g2[c] / sqrtf(v2[c] + BN_EPS);
        float y = __fadd_rn(__fmul_rn(__fsub_rn(__fadd_rn((float)S, conv_b[c]), m2[c]), scl), b2[c]);
        if (y > 0.f) atomicMin(&s_thrA[c], S);
        if (y < 0.f) atomicMax(&s_thrB[c], S);
    }
    if (tid >= 448 && tid < 453) {              // conv BN consts (fallback path)
        const int c = tid - 448;
        float scl = g2[c] / sqrtf(v2[c] + BN_EPS);
        s_bn2[c] = make_float4(conv_b[c], m2[c], scl, b2[c]);
    }
    if (tid >= 456 && tid < 466) {              // fc BN fold
        const int j = tid - 456;
        float s = g1[j] / sqrtf(v1[j] + BN_EPS);
        s_fcz[j] = make_float2(s, (fc_b[j] - m1[j]) * s + b1[j]);
    }

    // ---- issue the 25 coalesced image loads (in flight across the barrier) ----
    uint32_t u[25];
    #pragma unroll
    for (int j = 0; j < 24; j++) u[j] = __float_as_uint(xb[j * 32 + lane]);
    u[24] = (lane < 16) ? __float_as_uint(xb[768 + lane]) : 0x3F800000u;

    __syncthreads();

    // simple flag: per-channel "no S gives y==0 and scale>0" (warp-uniform smem reads)
    bool simple = true;
    #pragma unroll
    for (int c = 0; c < 5; c++)
        simple = simple && (s_bn2[c].z > 0.f) && (s_thrA[c] == s_thrB[c] + 2);

    // ---- exact-zero detect ----
    float za = 1.0f;
    #pragma unroll
    for (int j = 0; j < 25; j++)
        za = fminf(za, fabsf(__uint_as_float(u[j])));
    const bool anyzero = __ballot_sync(FULL, za == 0.0f) != 0;

    // ---- 25 sign ballots -> stream word L in lane L ----
    uint32_t myword = 0;
    #pragma unroll
    for (int k = 0; k < 6; k++) {
        uint32_t b0 = __ballot_sync(FULL, (int)u[4 * k + 0] < 0);
        uint32_t b1 = __ballot_sync(FULL, (int)u[4 * k + 1] < 0);
        uint32_t b2 = __ballot_sync(FULL, (int)u[4 * k + 2] < 0);
        uint32_t b3 = __ballot_sync(FULL, (int)u[4 * k + 3] < 0);
        uint32_t lo = (lane & 1) ? b1 : b0;
        uint32_t hi = (lane & 1) ? b3 : b2;
        uint32_t v  = (lane & 2) ? hi : lo;
        if ((lane >> 2) == k) myword = v;
    }
    {
        uint32_t b = __ballot_sync(FULL, (int)u[24] < 0);
        if (lane == 24) myword = b;
    }

    // ---- row r in lane r: 28 bits <<2 ----
    uint32_t rowreg;
    {
        int r  = (lane < 28) ? lane : 27;
        int bp = 28 * r;
        uint32_t lo = __shfl_sync(FULL, myword, bp >> 5);
        uint32_t hi = __shfl_sync(FULL, myword, (bp >> 5) + 1);
        rowreg = (__funnelshift_r(lo, hi, bp) & 0x0FFFFFFFu) << 2;
    }

    const int p   = (lane < 25) ? lane : 24;
    const int oy  = p / 5, ox = p % 5;
    const int sh6 = 6 * ox;

    uint2 cw0 = make_uint2(s_cwlo[0], s_cwhi[0]);
    uint2 cw1 = make_uint2(s_cwlo[1], s_cwhi[1]);
    uint2 cw2 = make_uint2(s_cwlo[2], s_cwhi[2]);
    uint2 cw3 = make_uint2(s_cwlo[3], s_cwhi[3]);
    uint2 cw4 = make_uint2(s_cwlo[4], s_cwhi[4]);

    int S0, S1, S2, S3, S4;

    if (!anyzero) {
        // ================= FAST PATH =================
        uint32_t xlo = 0;
        #pragma unroll
        for (int ky = 0; ky < 5; ky++) {
            int rl = 6 * oy - 2 + ky;
            uint32_t rv = __shfl_sync(FULL, rowreg, rl < 0 ? 0 : rl);
            xlo |= ((rv >> sh6) & 0x3Fu) << (6 * ky);
        }
        uint32_t xhi = (__shfl_sync(FULL, rowreg, 6 * oy + 3) >> sh6) & 0x3Fu;

        uint32_t cm  = (ox == 0) ? 0x3Cu : 0x3Fu;
        uint32_t Mlo = cm * 0x01041041u;
        if (oy == 0) Mlo &= 0xFFFFF000u;
        uint32_t Mhi = cm;
        int pm = ((oy == 0) ? 4 : 6) * ((ox == 0) ? 4 : 6);

        S0 = 2 * (int)(__popc((xlo ^ cw0.x) & Mlo) + __popc((xhi ^ cw0.y) & Mhi)) - pm;
        S1 = 2 * (int)(__popc((xlo ^ cw1.x) & Mlo) + __popc((xhi ^ cw1.y) & Mhi)) - pm;
        S2 = 2 * (int)(__popc((xlo ^ cw2.x) & Mlo) + __popc((xhi ^ cw2.y) & Mhi)) - pm;
        S3 = 2 * (int)(__popc((xlo ^ cw3.x) & Mlo) + __popc((xhi ^ cw3.y) & Mhi)) - pm;
        S4 = 2 * (int)(__popc((xlo ^ cw4.x) & Mlo) + __popc((xhi ^ cw4.y) & Mhi)) - pm;
    } else {
        // ===== SLOW PATH (image has exact-zero pixel; essentially never) =====
        S0 = S1 = S2 = S3 = S4 = 0;
        #pragma unroll 1
        for (int ky = 0; ky < 6; ky++) {
            int r = 6 * oy - 2 + ky;
            if (r < 0 || r >= 28) continue;
            #pragma unroll 1
            for (int kx = 0; kx < 6; kx++) {
                int c2 = 6 * ox - 2 + kx;
                if (c2 < 0 || c2 >= 28) continue;
                float f = xb[r * 28 + c2];
                int sx = (f > 0.f) - (f < 0.f);
                int bit = 6 * ky + kx;
                int w0 = (ky < 5) ? (int)((cw0.x >> bit) & 1) : (int)((cw0.y >> kx) & 1);
                int w1 = (ky < 5) ? (int)((cw1.x >> bit) & 1) : (int)((cw1.y >> kx) & 1);
                int w2 = (ky < 5) ? (int)((cw2.x >> bit) & 1) : (int)((cw2.y >> kx) & 1);
                int w3 = (ky < 5) ? (int)((cw3.x >> bit) & 1) : (int)((cw3.y >> kx) & 1);
                int w4 = (ky < 5) ? (int)((cw4.x >> bit) & 1) : (int)((cw4.y >> kx) & 1);
                S0 += w0 ? sx : -sx;
                S1 += w1 ? sx : -sx;
                S2 += w2 ? sx : -sx;
                S3 += w3 ? sx : -sx;
                S4 += w4 ? sx : -sx;
            }
        }
    }

    // ---- hardtanh-sign + binary FC ----
    const bool act = (lane < 25);
    const int  j   = (lane < 10) ? lane : 0;

    uint32_t fw0 = s_fcw[j][0], fw1 = s_fcw[j][1], fw2 = s_fcw[j][2],
             fw3 = s_fcw[j][3], fw4 = s_fcw[j][4];

    int dot;
    if (simple) {
        int A0 = s_thrA[0], A1 = s_thrA[1], A2 = s_thrA[2],
            A3 = s_thrA[3], A4 = s_thrA[4];
        int E = 0;
        E += __popc((__ballot_sync(FULL, act && (S0 >= A0)) ^ fw0) & 0x1FFFFFFu);
        E += __popc((__ballot_sync(FULL, act && (S1 >= A1)) ^ fw1) & 0x1FFFFFFu);
        E += __popc((__ballot_sync(FULL, act && (S2 >= A2)) ^ fw2) & 0x1FFFFFFu);
        E += __popc((__ballot_sync(FULL, act && (S3 >= A3)) ^ fw3) & 0x1FFFFFFu);
        E += __popc((__ballot_sync(FULL, act && (S4 >= A4)) ^ fw4) & 0x1FFFFFFu);
        dot = 125 - 2 * E;
    } else {
        int SS[5] = {S0, S1, S2, S3, S4};
        uint32_t fw[5] = {fw0, fw1, fw2, fw3, fw4};
        int D = 0, pmf = 0;
        #pragma unroll
        for (int c = 0; c < 5; c++) {
            float4 bn = s_bn2[c];
            float Sf = (float)SS[c];
            float y = __fadd_rn(__fmul_rn(__fsub_rn(__fadd_rn(Sf, bn.x), bn.y), bn.z), bn.w);
            uint32_t pb = __ballot_sync(FULL, act && (y > 0.f));
            uint32_t nb = __ballot_sync(FULL, act && (y < 0.f));
            uint32_t mm = pb | nb;
            pmf += __popc(mm);
            D   += __popc(~(pb ^ fw[c]) & mm);
        }
        dot = 2 * D - pmf;
    }

    float2 fz = s_fcz[j];
    float z = fmaf((float)dot, fz.x, fz.y);

    // ---- log_softmax over 10 lanes (width-16 butterflies) ----
    float zv = (lane < 10) ? z : -INFINITY;
    float m = zv;
    #pragma unroll
    for (int o = 8; o; o >>= 1) m = fmaxf(m, __shfl_xor_sync(FULL, m, o, 16));
    float e = __expf(zv - m);
    float se = e;
    #pragma unroll
    for (int o = 8; o; o >>= 1) se += __shfl_xor_sync(FULL, se, o, 16);

    if (valid && lane < 10) out[(size_t)img * 10 + lane] = zv - m - __logf(se);
}

extern "C" void kernel_launch(void* const* d_in, const int* in_sizes, int n_in,
                              void* d_out, int out_size)
{
    const float* x = (const float*)d_in[0];
    int B = in_sizes[0] / 784;

    bnn_kernel<<<(B + 15) / 16, 512>>>(
        x,
        (const float*)d_in[1], (const float*)d_in[2],
        (const float*)d_in[3], (const float*)d_in[4],
        (const float*)d_in[5], (const float*)d_in[6],
        (const float*)d_in[7], (const float*)d_in[8],
        (const float*)d_in[9], (const float*)d_in[10],
        (const float*)d_in[11], (const float*)d_in[12],
        (float*)d_out, B);
}